// round 14
// baseline (speedup 1.0000x reference)
#include <cuda_runtime.h>
#include <cuda_fp16.h>
#include <math.h>
#include <stdint.h>

#define SN 6400
#define CC 256
#define NBATCH 2
#define LOG2E10 14.426950408889634f    // 10 * log2(e)

// ---------------- scratch (device globals; no allocation allowed) ----------
__device__ __align__(16) __half g_A[NBATCH * SN * CC];    // normalized I, fp16
__device__ __align__(16) __half g_B[NBATCH * SN * CC];    // normalized T, fp16
__device__ __align__(16) __half g_rawh[(size_t)NBATCH * SN * SN]; // raw matrix fp16
__device__ float    g_mean[CC];
__device__ unsigned g_rowmin[NBATCH * SN];                // row min bits (raw>=0)
__device__ unsigned g_colmax[NBATCH * SN];                // encoded float max

// order-preserving float <-> uint encoding (atomicMax on floats)
__device__ __forceinline__ unsigned enc_f(float f) {
    unsigned u = __float_as_uint(f);
    return (u & 0x80000000u) ? ~u : (u | 0x80000000u);
}
__device__ __forceinline__ float dec_f(unsigned u) {
    u = (u & 0x80000000u) ? (u ^ 0x80000000u) : ~u;
    return __uint_as_float(u);
}

// fast exp2 via MUFU (device-guaranteed, independent of fast-math flags)
__device__ __forceinline__ float ex2(float x) {
    float r;
    asm("ex2.approx.f32 %0, %1;" : "=f"(r) : "f"(x));
    return r;
}

// ---------------- PTX helpers (plain sm_80-era, no arch-variant gating) ----
__device__ __forceinline__ uint32_t smem_u32(const void* p) {
    uint32_t a;
    asm("{ .reg .u64 t; cvta.to.shared.u64 t, %1; cvt.u32.u64 %0, t; }" : "=r"(a) : "l"(p));
    return a;
}
__device__ __forceinline__ void cp16(uint32_t dst, const void* src) {
    asm volatile("cp.async.cg.shared.global [%0], [%1], 16;" :: "r"(dst), "l"(src));
}
#define CP_COMMIT() asm volatile("cp.async.commit_group;" ::: "memory")
#define CP_WAIT2()  asm volatile("cp.async.wait_group 2;" ::: "memory")

__device__ __forceinline__ void ldsm4(uint32_t r[4], uint32_t a) {
    asm volatile("ldmatrix.sync.aligned.m8n8.x4.shared.b16 {%0,%1,%2,%3}, [%4];"
        : "=r"(r[0]), "=r"(r[1]), "=r"(r[2]), "=r"(r[3]) : "r"(a));
}
__device__ __forceinline__ void mma_f16(float d[4], const uint32_t a[4],
                                        uint32_t b0, uint32_t b1) {
    asm volatile("mma.sync.aligned.m16n8k16.row.col.f32.f16.f16.f32 "
        "{%0,%1,%2,%3}, {%4,%5,%6,%7}, {%8,%9}, {%0,%1,%2,%3};"
        : "+f"(d[0]), "+f"(d[1]), "+f"(d[2]), "+f"(d[3])
        : "r"(a[0]), "r"(a[1]), "r"(a[2]), "r"(a[3]), "r"(b0), "r"(b1));
}
// SW128 xor swizzle for 128B rows: bits[6:4] ^= bits[9:7]
__device__ __forceinline__ uint32_t sw128(uint32_t o) {
    return o ^ (((o >> 7) & 7u) << 4);
}

// ---------------- kernel 1: per-channel mean of T over (n,h,w) -------------
__global__ void k_mean(const float* __restrict__ T) {
    int c = blockIdx.x;
    float s = 0.f;
    const float* p0 = T + (size_t)c * SN;
    const float* p1 = T + (size_t)(CC + c) * SN;
    for (int idx = threadIdx.x; idx < SN; idx += 256) s += p0[idx] + p1[idx];
    __shared__ float sh[256];
    sh[threadIdx.x] = s;
    __syncthreads();
    for (int o = 128; o > 0; o >>= 1) {
        if (threadIdx.x < o) sh[threadIdx.x] += sh[threadIdx.x + o];
        __syncthreads();
    }
    if (threadIdx.x == 0) g_mean[c] = sh[0] * (1.f / (NBATCH * SN));
}

// ---------------- kernel 2: center, normalize, fp16 out; init minima -------
__global__ void __launch_bounds__(256) k_norm(const float* __restrict__ I,
                                              const float* __restrict__ T) {
    __shared__ float smI[256][33];
    __shared__ float smT[256][33];
    __shared__ float part[2][32][8];
    __shared__ float rs[32][2];

    int n  = blockIdx.y;
    int s0 = blockIdx.x * 32;
    int tid = threadIdx.x;

    if (tid < 32) {
        g_colmax[n * SN + s0 + tid] = enc_f(-1e30f);
        g_rowmin[n * SN + s0 + tid] = 0x7F800000u;   // +inf
    }

#pragma unroll
    for (int it = 0; it < 32; it++) {
        int e = tid + it * 256;
        int c = e >> 5;
        int s = e & 31;
        float m = g_mean[c];
        size_t ga = ((size_t)n * CC + c) * SN + s0 + s;
        smI[c][s] = I[ga] - m;
        smT[c][s] = T[ga] - m;
    }
    __syncthreads();
    {
        int s = tid & 31;
        int p = tid >> 5;
        float si = 0.f, st = 0.f;
#pragma unroll
        for (int q = 0; q < 32; q++) {
            int c = p * 32 + q;
            float a = smI[c][s];
            float b = smT[c][s];
            si += a * a;
            st += b * b;
        }
        part[0][s][p] = si;
        part[1][s][p] = st;
    }
    __syncthreads();
    if (tid < 32) {
        float si = 0.f, st = 0.f;
#pragma unroll
        for (int p = 0; p < 8; p++) { si += part[0][tid][p]; st += part[1][tid][p]; }
        rs[tid][0] = rsqrtf(si);
        rs[tid][1] = rsqrtf(st);
    }
    __syncthreads();
#pragma unroll
    for (int it = 0; it < 16; it++) {
        int e = tid + it * 256;
        int s  = e >> 7;
        int cp = (e & 127) * 2;
        float ri = rs[s][0];
        float rt = rs[s][1];
        size_t ob = ((size_t)n * SN + s0 + s) * CC + cp;
        *(__half2*)(g_A + ob) = __floats2half2_rn(smI[cp][s] * ri, smI[cp + 1][s] * ri);
        *(__half2*)(g_B + ob) = __floats2half2_rn(smT[cp][s] * rt, smT[cp + 1][s] * rt);
    }
}

// ---------------- kernel 3: fp16 mma GEMM (fp32 acc), rawh + row minima ----
// CTA tile 128x128, BK=64 (128B rows, SW128), 3-stage cp.async pipeline
#define TILE_B 16384               // 128 rows x 128 bytes
#define STAGE_B (2 * TILE_B)       // A, B
#define NSTAGE 3
#define GEMM_SMEM (NSTAGE * STAGE_B)   // 96 KB

__global__ void __launch_bounds__(256, 2) k_gemm_mma() {
    extern __shared__ __align__(1024) char smb[];
    int tid = threadIdx.x;
    int wid = tid >> 5;
    int l   = tid & 31;
    int n  = blockIdx.z;
    int i0 = blockIdx.y * 128;
    int j0 = blockIdx.x * 128;
    uint32_t sbase = smem_u32(smb);

    auto load_stage = [&](int kc, int s) {
        int k0 = kc * 64;
        uint32_t b = sbase + s * STAGE_B;
#pragma unroll
        for (int i = 0; i < 4; i++) {
            int e   = tid + i * 256;
            int row = e >> 3;
            int ch  = e & 7;
            uint32_t so = sw128((uint32_t)(row * 128 + ch * 16));
            cp16(b + so,          g_A + (size_t)(n * SN + i0 + row) * CC + k0 + ch * 8);
            cp16(b + TILE_B + so, g_B + (size_t)(n * SN + j0 + row) * CC + k0 + ch * 8);
        }
        CP_COMMIT();
    };

    float acc[2][8][4];
#pragma unroll
    for (int a = 0; a < 2; a++)
#pragma unroll
        for (int g = 0; g < 8; g++)
#pragma unroll
            for (int q = 0; q < 4; q++) acc[a][g][q] = 0.f;

    int wm = wid >> 1;
    int wn = wid & 1;
    int mb = wm * 32;
    int nb = wn * 64;

    int a_row0 = mb + (l & 15);
    int a_ch   = l >> 4;
    int b_ch   = (l >> 3) & 1;
    int b_rowq = nb + (l & 7) + ((l >> 4) << 3);

    load_stage(0, 0);
    load_stage(1, 1);
    load_stage(2, 2);

#pragma unroll
    for (int kc = 0; kc < 4; kc++) {
        CP_WAIT2();
        __syncthreads();
        uint32_t b = sbase + (kc % NSTAGE) * STAGE_B;
#pragma unroll
        for (int ks = 0; ks < 4; ks++) {
            uint32_t ah[2][4], bt[4][4];
#pragma unroll
            for (int mt = 0; mt < 2; mt++) {
                uint32_t off = sw128((uint32_t)((a_row0 + mt * 16) * 128 + ks * 32 + a_ch * 16));
                ldsm4(ah[mt], b + off);
            }
#pragma unroll
            for (int ng = 0; ng < 4; ng++) {
                uint32_t off = sw128((uint32_t)((b_rowq + ng * 16) * 128 + ks * 32 + b_ch * 16));
                ldsm4(bt[ng], b + TILE_B + off);
            }
#pragma unroll
            for (int mt = 0; mt < 2; mt++)
#pragma unroll
                for (int ng = 0; ng < 4; ng++) {
                    mma_f16(acc[mt][2 * ng],     ah[mt], bt[ng][0], bt[ng][1]);
                    mma_f16(acc[mt][2 * ng + 1], ah[mt], bt[ng][2], bt[ng][3]);
                }
        }
        __syncthreads();
        if (kc + 3 < 4) load_stage(kc + 3, kc % NSTAGE);
        else            CP_COMMIT();       // keep group FIFO advancing
    }

    // ---- epilogue: rawh = clip((1-cos)/2, 0) + per-row min -> g_rowmin ----
    __half* out = g_rawh + (size_t)n * SN * SN;
    int r0 = i0 + mb + (l >> 2);
    int c0 = j0 + nb + (l & 3) * 2;
#pragma unroll
    for (int mt = 0; mt < 2; mt++) {
        int r = r0 + mt * 16;
        float rm0 = 1e30f, rm1 = 1e30f;
#pragma unroll
        for (int g = 0; g < 8; g++) {
            int c = c0 + g * 8;
            float v0 = fmaxf(0.5f * (1.f - acc[mt][g][0]), 0.f);
            float v1 = fmaxf(0.5f * (1.f - acc[mt][g][1]), 0.f);
            float v2 = fmaxf(0.5f * (1.f - acc[mt][g][2]), 0.f);
            float v3 = fmaxf(0.5f * (1.f - acc[mt][g][3]), 0.f);
            rm0 = fminf(rm0, fminf(v0, v1));
            rm1 = fminf(rm1, fminf(v2, v3));
            *(__half2*)(out + (size_t)r * SN + c)       = __floats2half2_rn(v0, v1);
            *(__half2*)(out + (size_t)(r + 8) * SN + c) = __floats2half2_rn(v2, v3);
        }
        // quad reduce (lanes l^1, l^2 share the same rows)
#pragma unroll
        for (int o = 1; o <= 2; o <<= 1) {
            rm0 = fminf(rm0, __shfl_xor_sync(~0u, rm0, o));
            rm1 = fminf(rm1, __shfl_xor_sync(~0u, rm1, o));
        }
        if ((l & 3) == 0) {
            atomicMin(&g_rowmin[n * SN + r],     __float_as_uint(rm0));
            atomicMin(&g_rowmin[n * SN + r + 8], __float_as_uint(rm1));
        }
    }
}

// ---------------- kernel 4: fused Z + column max (row min precomputed) -----
// 320 threads, 32 rows/block, 2 rows per iter, ONE barrier per iter.
// Blocks scheduled in REVERSE row order: GEMM wrote g_rawh ascending, so the
// tail (~120MB) is L2-resident; reading it first converts misses to hits.
// Rows loaded as uint2 (LDG.64).
#define RPB 32
__global__ void __launch_bounds__(320, 3) k_stats() {
    __shared__ float red_z[2][2][10];    // [parity][row-of-pair][warp]

    int tid  = threadIdx.x;
    int lane = tid & 31;
    int warp = tid >> 5;                 // 0..9
    int blk  = gridDim.x - 1 - blockIdx.x;   // reverse order
    int rbase = blk * RPB;               // global row id
    int n = rbase / SN;

    __half2 cm[10];
#pragma unroll
    for (int q = 0; q < 10; q++) cm[q] = __float2half2_rn(-60000.f);

    const uint2* rowbase = (const uint2*)(g_rawh + (size_t)rbase * SN);

    for (int r = 0; r < RPB; r += 2) {
        int par = (r >> 1) & 1;
        const uint2* row0 = rowbase + (size_t)r * (SN / 4);
        const uint2* row1 = row0 + (SN / 4);
        __half2 v[10], w[10];
#pragma unroll
        for (int q = 0; q < 5; q++) {
            uint2 t0 = row0[tid + q * 320];
            uint2 t1 = row1[tid + q * 320];
            v[2 * q]     = *(__half2*)&t0.x;
            v[2 * q + 1] = *(__half2*)&t0.y;
            w[2 * q]     = *(__half2*)&t1.x;
            w[2 * q + 1] = *(__half2*)&t1.y;
        }

        // a2 = 10*log2(e)/(rmin+eps); exponent in base 2
        float av = LOG2E10 / (__uint_as_float(g_rowmin[rbase + r])     + 1e-5f);
        float aw = LOG2E10 / (__uint_as_float(g_rowmin[rbase + r + 1]) + 1e-5f);

        float zv = 0.f, zw = 0.f;
#pragma unroll
        for (int q = 0; q < 10; q++) {
            float2 fv = __half22float2(v[q]);
            float2 fw = __half22float2(w[q]);
            zv += ex2(LOG2E10 - av * fv.x) + ex2(LOG2E10 - av * fv.y);
            zw += ex2(LOG2E10 - aw * fw.x) + ex2(LOG2E10 - aw * fw.y);
        }
#pragma unroll
        for (int o = 16; o > 0; o >>= 1) {
            zv += __shfl_xor_sync(~0u, zv, o);
            zw += __shfl_xor_sync(~0u, zw, o);
        }
        if (lane == 0) { red_z[par][0][warp] = zv; red_z[par][1][warp] = zw; }
        __syncthreads();
        float Zv = red_z[par][0][0], Zw = red_z[par][1][0];
#pragma unroll
        for (int x = 1; x < 10; x++) { Zv += red_z[par][0][x]; Zw += red_z[par][1][x]; }
        float c0v = LOG2E10 - __log2f(Zv);   // log2-space offset
        float c0w = LOG2E10 - __log2f(Zw);

#pragma unroll
        for (int q = 0; q < 10; q++) {
            float2 fv = __half22float2(v[q]);
            float2 fw = __half22float2(w[q]);
            cm[q] = __hmax2(cm[q], __floats2half2_rn(c0v - av * fv.x, c0v - av * fv.y));
            cm[q] = __hmax2(cm[q], __floats2half2_rn(c0w - aw * fw.x, c0w - aw * fw.y));
        }
    }

#pragma unroll
    for (int q = 0; q < 10; q++) {
        float2 f = __half22float2(cm[q]);   // log2-space colmax
        int j = 4 * (tid + (q >> 1) * 320) + (q & 1) * 2;
        atomicMax(&g_colmax[n * SN + j],     enc_f(f.x));
        atomicMax(&g_colmax[n * SN + j + 1], enc_f(f.y));
    }
}

// ---------------- kernel 5: final reduction -> loss (base-2 colmax) --------
__global__ void k_final(float* __restrict__ out) {
    __shared__ float2 sh[256];
    int tid = threadIdx.x;
    float s0 = 0.f, s1 = 0.f;
    for (int j = tid; j < SN; j += 256) {
        s0 += ex2(dec_f(g_colmax[j]));
        s1 += ex2(dec_f(g_colmax[SN + j]));
    }
    sh[tid] = make_float2(s0, s1);
    __syncthreads();
    for (int o = 128; o > 0; o >>= 1) {
        if (tid < o) { sh[tid].x += sh[tid + o].x; sh[tid].y += sh[tid + o].y; }
        __syncthreads();
    }
    if (tid == 0) {
        float cs0 = sh[0].x * (1.f / SN);
        float cs1 = sh[0].y * (1.f / SN);
        out[0] = -0.5f * (logf(cs0) + logf(cs1));
    }
}

// ---------------- launcher --------------------------------------------------
extern "C" void kernel_launch(void* const* d_in, const int* in_sizes, int n_in,
                              void* d_out, int out_size) {
    const float* I = (const float*)d_in[0];
    const float* T = (const float*)d_in[1];
    float* out = (float*)d_out;

    cudaFuncSetAttribute(k_gemm_mma, cudaFuncAttributeMaxDynamicSharedMemorySize, GEMM_SMEM);

    k_mean<<<CC, 256>>>(T);
    k_norm<<<dim3(SN / 32, NBATCH), 256>>>(I, T);
    dim3 gg(SN / 128, SN / 128, NBATCH);
    k_gemm_mma<<<gg, 256, GEMM_SMEM>>>();
    k_stats<<<NBATCH * SN / RPB, 320>>>();
    k_final<<<1, 256>>>(out);
}

// round 15
// speedup vs baseline: 1.0226x; 1.0226x over previous
#include <cuda_runtime.h>
#include <cuda_fp16.h>
#include <math.h>
#include <stdint.h>

#define SN 6400
#define CC 256
#define NBATCH 2
#define LOG2E10 14.426950408889634f    // 10 * log2(e)

// ---------------- scratch (device globals; no allocation allowed) ----------
__device__ __align__(16) __half g_A[NBATCH * SN * CC];    // normalized I, fp16
__device__ __align__(16) __half g_B[NBATCH * SN * CC];    // normalized T, fp16
__device__ __align__(16) __half g_rawh[(size_t)NBATCH * SN * SN]; // raw matrix fp16
__device__ float    g_mean[CC];
__device__ unsigned g_rowmin[NBATCH * SN];                // row min bits (raw>=0)
__device__ unsigned g_colmax[NBATCH * SN];                // encoded float max

// order-preserving float <-> uint encoding (atomicMax on floats)
__device__ __forceinline__ unsigned enc_f(float f) {
    unsigned u = __float_as_uint(f);
    return (u & 0x80000000u) ? ~u : (u | 0x80000000u);
}
__device__ __forceinline__ float dec_f(unsigned u) {
    u = (u & 0x80000000u) ? (u ^ 0x80000000u) : ~u;
    return __uint_as_float(u);
}

// fast exp2 via MUFU (device-guaranteed, independent of fast-math flags)
__device__ __forceinline__ float ex2(float x) {
    float r;
    asm("ex2.approx.f32 %0, %1;" : "=f"(r) : "f"(x));
    return r;
}

// ---------------- PTX helpers (plain sm_80-era, no arch-variant gating) ----
__device__ __forceinline__ uint32_t smem_u32(const void* p) {
    uint32_t a;
    asm("{ .reg .u64 t; cvta.to.shared.u64 t, %1; cvt.u32.u64 %0, t; }" : "=r"(a) : "l"(p));
    return a;
}
__device__ __forceinline__ void cp16(uint32_t dst, const void* src) {
    asm volatile("cp.async.cg.shared.global [%0], [%1], 16;" :: "r"(dst), "l"(src));
}
#define CP_COMMIT() asm volatile("cp.async.commit_group;" ::: "memory")
#define CP_WAIT2()  asm volatile("cp.async.wait_group 2;" ::: "memory")

__device__ __forceinline__ void ldsm4(uint32_t r[4], uint32_t a) {
    asm volatile("ldmatrix.sync.aligned.m8n8.x4.shared.b16 {%0,%1,%2,%3}, [%4];"
        : "=r"(r[0]), "=r"(r[1]), "=r"(r[2]), "=r"(r[3]) : "r"(a));
}
__device__ __forceinline__ void mma_f16(float d[4], const uint32_t a[4],
                                        uint32_t b0, uint32_t b1) {
    asm volatile("mma.sync.aligned.m16n8k16.row.col.f32.f16.f16.f32 "
        "{%0,%1,%2,%3}, {%4,%5,%6,%7}, {%8,%9}, {%0,%1,%2,%3};"
        : "+f"(d[0]), "+f"(d[1]), "+f"(d[2]), "+f"(d[3])
        : "r"(a[0]), "r"(a[1]), "r"(a[2]), "r"(a[3]), "r"(b0), "r"(b1));
}
// SW128 xor swizzle for 128B rows: bits[6:4] ^= bits[9:7]
__device__ __forceinline__ uint32_t sw128(uint32_t o) {
    return o ^ (((o >> 7) & 7u) << 4);
}

// ---------------- kernel 1: per-channel mean of T over (n,h,w) -------------
__global__ void k_mean(const float* __restrict__ T) {
    int c = blockIdx.x;
    float s = 0.f;
    const float* p0 = T + (size_t)c * SN;
    const float* p1 = T + (size_t)(CC + c) * SN;
    for (int idx = threadIdx.x; idx < SN; idx += 256) s += p0[idx] + p1[idx];
    __shared__ float sh[256];
    sh[threadIdx.x] = s;
    __syncthreads();
    for (int o = 128; o > 0; o >>= 1) {
        if (threadIdx.x < o) sh[threadIdx.x] += sh[threadIdx.x + o];
        __syncthreads();
    }
    if (threadIdx.x == 0) g_mean[c] = sh[0] * (1.f / (NBATCH * SN));
}

// ---------------- kernel 2: center, normalize, fp16 out; init minima -------
// load phase vectorized: float4 LDG.128, conflict-free smem scatter
__global__ void __launch_bounds__(256) k_norm(const float* __restrict__ I,
                                              const float* __restrict__ T) {
    __shared__ float smI[256][33];
    __shared__ float smT[256][33];
    __shared__ float part[2][32][8];
    __shared__ float rs[32][2];

    int n  = blockIdx.y;
    int s0 = blockIdx.x * 32;
    int tid = threadIdx.x;

    if (tid < 32) {
        g_colmax[n * SN + s0 + tid] = enc_f(-1e30f);
        g_rowmin[n * SN + s0 + tid] = 0x7F800000u;   // +inf
    }

#pragma unroll
    for (int it = 0; it < 8; it++) {
        int e  = tid + it * 256;            // 0..2047 granules
        int c  = e >> 3;                    // channel
        int s4 = (e & 7) * 4;               // 4 consecutive s
        float m = g_mean[c];
        size_t ga = ((size_t)n * CC + c) * SN + s0 + s4;
        float4 iv = *(const float4*)(I + ga);
        float4 tv = *(const float4*)(T + ga);
        smI[c][s4 + 0] = iv.x - m; smI[c][s4 + 1] = iv.y - m;
        smI[c][s4 + 2] = iv.z - m; smI[c][s4 + 3] = iv.w - m;
        smT[c][s4 + 0] = tv.x - m; smT[c][s4 + 1] = tv.y - m;
        smT[c][s4 + 2] = tv.z - m; smT[c][s4 + 3] = tv.w - m;
    }
    __syncthreads();
    {
        int s = tid & 31;
        int p = tid >> 5;
        float si = 0.f, st = 0.f;
#pragma unroll
        for (int q = 0; q < 32; q++) {
            int c = p * 32 + q;
            float a = smI[c][s];
            float b = smT[c][s];
            si += a * a;
            st += b * b;
        }
        part[0][s][p] = si;
        part[1][s][p] = st;
    }
    __syncthreads();
    if (tid < 32) {
        float si = 0.f, st = 0.f;
#pragma unroll
        for (int p = 0; p < 8; p++) { si += part[0][tid][p]; st += part[1][tid][p]; }
        rs[tid][0] = rsqrtf(si);
        rs[tid][1] = rsqrtf(st);
    }
    __syncthreads();
#pragma unroll
    for (int it = 0; it < 16; it++) {
        int e = tid + it * 256;
        int s  = e >> 7;
        int cp = (e & 127) * 2;
        float ri = rs[s][0];
        float rt = rs[s][1];
        size_t ob = ((size_t)n * SN + s0 + s) * CC + cp;
        *(__half2*)(g_A + ob) = __floats2half2_rn(smI[cp][s] * ri, smI[cp + 1][s] * ri);
        *(__half2*)(g_B + ob) = __floats2half2_rn(smT[cp][s] * rt, smT[cp + 1][s] * rt);
    }
}

// ---------------- kernel 3: fp16 mma GEMM (fp32 acc), rawh + row minima ----
// CTA tile 128x128, BK=64 (128B rows, SW128), 3-stage cp.async pipeline
#define TILE_B 16384               // 128 rows x 128 bytes
#define STAGE_B (2 * TILE_B)       // A, B
#define NSTAGE 3
#define GEMM_SMEM (NSTAGE * STAGE_B)   // 96 KB

__global__ void __launch_bounds__(256, 2) k_gemm_mma() {
    extern __shared__ __align__(1024) char smb[];
    int tid = threadIdx.x;
    int wid = tid >> 5;
    int l   = tid & 31;
    int n  = blockIdx.z;
    int i0 = blockIdx.y * 128;
    int j0 = blockIdx.x * 128;
    uint32_t sbase = smem_u32(smb);

    auto load_stage = [&](int kc, int s) {
        int k0 = kc * 64;
        uint32_t b = sbase + s * STAGE_B;
#pragma unroll
        for (int i = 0; i < 4; i++) {
            int e   = tid + i * 256;
            int row = e >> 3;
            int ch  = e & 7;
            uint32_t so = sw128((uint32_t)(row * 128 + ch * 16));
            cp16(b + so,          g_A + (size_t)(n * SN + i0 + row) * CC + k0 + ch * 8);
            cp16(b + TILE_B + so, g_B + (size_t)(n * SN + j0 + row) * CC + k0 + ch * 8);
        }
        CP_COMMIT();
    };

    float acc[2][8][4];
#pragma unroll
    for (int a = 0; a < 2; a++)
#pragma unroll
        for (int g = 0; g < 8; g++)
#pragma unroll
            for (int q = 0; q < 4; q++) acc[a][g][q] = 0.f;

    int wm = wid >> 1;
    int wn = wid & 1;
    int mb = wm * 32;
    int nb = wn * 64;

    int a_row0 = mb + (l & 15);
    int a_ch   = l >> 4;
    int b_ch   = (l >> 3) & 1;
    int b_rowq = nb + (l & 7) + ((l >> 4) << 3);

    load_stage(0, 0);
    load_stage(1, 1);
    load_stage(2, 2);

#pragma unroll
    for (int kc = 0; kc < 4; kc++) {
        CP_WAIT2();
        __syncthreads();
        uint32_t b = sbase + (kc % NSTAGE) * STAGE_B;
#pragma unroll
        for (int ks = 0; ks < 4; ks++) {
            uint32_t ah[2][4], bt[4][4];
#pragma unroll
            for (int mt = 0; mt < 2; mt++) {
                uint32_t off = sw128((uint32_t)((a_row0 + mt * 16) * 128 + ks * 32 + a_ch * 16));
                ldsm4(ah[mt], b + off);
            }
#pragma unroll
            for (int ng = 0; ng < 4; ng++) {
                uint32_t off = sw128((uint32_t)((b_rowq + ng * 16) * 128 + ks * 32 + b_ch * 16));
                ldsm4(bt[ng], b + TILE_B + off);
            }
#pragma unroll
            for (int mt = 0; mt < 2; mt++)
#pragma unroll
                for (int ng = 0; ng < 4; ng++) {
                    mma_f16(acc[mt][2 * ng],     ah[mt], bt[ng][0], bt[ng][1]);
                    mma_f16(acc[mt][2 * ng + 1], ah[mt], bt[ng][2], bt[ng][3]);
                }
        }
        __syncthreads();
        if (kc + 3 < 4) load_stage(kc + 3, kc % NSTAGE);
        else            CP_COMMIT();       // keep group FIFO advancing
    }

    // ---- epilogue: rawh = clip((1-cos)/2, 0) + per-row min -> g_rowmin ----
    __half* out = g_rawh + (size_t)n * SN * SN;
    int r0 = i0 + mb + (l >> 2);
    int c0 = j0 + nb + (l & 3) * 2;
#pragma unroll
    for (int mt = 0; mt < 2; mt++) {
        int r = r0 + mt * 16;
        float rm0 = 1e30f, rm1 = 1e30f;
#pragma unroll
        for (int g = 0; g < 8; g++) {
            int c = c0 + g * 8;
            float v0 = fmaxf(0.5f * (1.f - acc[mt][g][0]), 0.f);
            float v1 = fmaxf(0.5f * (1.f - acc[mt][g][1]), 0.f);
            float v2 = fmaxf(0.5f * (1.f - acc[mt][g][2]), 0.f);
            float v3 = fmaxf(0.5f * (1.f - acc[mt][g][3]), 0.f);
            rm0 = fminf(rm0, fminf(v0, v1));
            rm1 = fminf(rm1, fminf(v2, v3));
            *(__half2*)(out + (size_t)r * SN + c)       = __floats2half2_rn(v0, v1);
            *(__half2*)(out + (size_t)(r + 8) * SN + c) = __floats2half2_rn(v2, v3);
        }
        // quad reduce (lanes l^1, l^2 share the same rows)
#pragma unroll
        for (int o = 1; o <= 2; o <<= 1) {
            rm0 = fminf(rm0, __shfl_xor_sync(~0u, rm0, o));
            rm1 = fminf(rm1, __shfl_xor_sync(~0u, rm1, o));
        }
        if ((l & 3) == 0) {
            atomicMin(&g_rowmin[n * SN + r],     __float_as_uint(rm0));
            atomicMin(&g_rowmin[n * SN + r + 8], __float_as_uint(rm1));
        }
    }
}

// ---------------- kernel 4: fused Z + column max (row min precomputed) -----
// 320 threads, 32 rows/block, 2 rows per iter, ONE barrier per iter (parity
// double-buffered slots). Base-2 softmax. Regs capped for 3 CTAs/SM.
#define RPB 32
__global__ void __launch_bounds__(320, 3) k_stats() {
    __shared__ float red_z[2][2][10];    // [parity][row-of-pair][warp]

    int tid  = threadIdx.x;
    int lane = tid & 31;
    int warp = tid >> 5;                 // 0..9
    int rbase = blockIdx.x * RPB;        // global row id
    int n = rbase / SN;

    __half2 cm[10];
#pragma unroll
    for (int q = 0; q < 10; q++) cm[q] = __float2half2_rn(-60000.f);

    const __half2* rowbase = (const __half2*)g_rawh + (size_t)rbase * (SN / 2);

    for (int r = 0; r < RPB; r += 2) {
        int par = (r >> 1) & 1;
        const __half2* row0 = rowbase + (size_t)r * (SN / 2);
        const __half2* row1 = row0 + (SN / 2);
        __half2 v[10], w[10];
#pragma unroll
        for (int q = 0; q < 10; q++) { v[q] = row0[tid + q * 320]; w[q] = row1[tid + q * 320]; }

        // a2 = 10*log2(e)/(rmin+eps); exponent in base 2
        float av = LOG2E10 / (__uint_as_float(g_rowmin[rbase + r])     + 1e-5f);
        float aw = LOG2E10 / (__uint_as_float(g_rowmin[rbase + r + 1]) + 1e-5f);

        float zv = 0.f, zw = 0.f;
#pragma unroll
        for (int q = 0; q < 10; q++) {
            float2 fv = __half22float2(v[q]);
            float2 fw = __half22float2(w[q]);
            zv += ex2(LOG2E10 - av * fv.x) + ex2(LOG2E10 - av * fv.y);
            zw += ex2(LOG2E10 - aw * fw.x) + ex2(LOG2E10 - aw * fw.y);
        }
#pragma unroll
        for (int o = 16; o > 0; o >>= 1) {
            zv += __shfl_xor_sync(~0u, zv, o);
            zw += __shfl_xor_sync(~0u, zw, o);
        }
        if (lane == 0) { red_z[par][0][warp] = zv; red_z[par][1][warp] = zw; }
        __syncthreads();
        float Zv = red_z[par][0][0], Zw = red_z[par][1][0];
#pragma unroll
        for (int x = 1; x < 10; x++) { Zv += red_z[par][0][x]; Zw += red_z[par][1][x]; }
        float c0v = LOG2E10 - __log2f(Zv);   // log2-space offset
        float c0w = LOG2E10 - __log2f(Zw);

#pragma unroll
        for (int q = 0; q < 10; q++) {
            float2 fv = __half22float2(v[q]);
            float2 fw = __half22float2(w[q]);
            cm[q] = __hmax2(cm[q], __floats2half2_rn(c0v - av * fv.x, c0v - av * fv.y));
            cm[q] = __hmax2(cm[q], __floats2half2_rn(c0w - aw * fw.x, c0w - aw * fw.y));
        }
    }

#pragma unroll
    for (int q = 0; q < 10; q++) {
        float2 f = __half22float2(cm[q]);   // log2-space colmax
        int j = 2 * (tid + q * 320);
        atomicMax(&g_colmax[n * SN + j],     enc_f(f.x));
        atomicMax(&g_colmax[n * SN + j + 1], enc_f(f.y));
    }
}

// ---------------- kernel 5: final reduction -> loss (base-2 colmax) --------
__global__ void k_final(float* __restrict__ out) {
    __shared__ float2 sh[256];
    int tid = threadIdx.x;
    float s0 = 0.f, s1 = 0.f;
    for (int j = tid; j < SN; j += 256) {
        s0 += ex2(dec_f(g_colmax[j]));
        s1 += ex2(dec_f(g_colmax[SN + j]));
    }
    sh[tid] = make_float2(s0, s1);
    __syncthreads();
    for (int o = 128; o > 0; o >>= 1) {
        if (tid < o) { sh[tid].x += sh[tid + o].x; sh[tid].y += sh[tid + o].y; }
        __syncthreads();
    }
    if (tid == 0) {
        float cs0 = sh[0].x * (1.f / SN);
        float cs1 = sh[0].y * (1.f / SN);
        out[0] = -0.5f * (logf(cs0) + logf(cs1));
    }
}

// ---------------- launcher --------------------------------------------------
extern "C" void kernel_launch(void* const* d_in, const int* in_sizes, int n_in,
                              void* d_out, int out_size) {
    const float* I = (const float*)d_in[0];
    const float* T = (const float*)d_in[1];
    float* out = (float*)d_out;

    cudaFuncSetAttribute(k_gemm_mma, cudaFuncAttributeMaxDynamicSharedMemorySize, GEMM_SMEM);

    k_mean<<<CC, 256>>>(T);
    k_norm<<<dim3(SN / 32, NBATCH), 256>>>(I, T);
    dim3 gg(SN / 128, SN / 128, NBATCH);
    k_gemm_mma<<<gg, 256, GEMM_SMEM>>>();
    k_stats<<<NBATCH * SN / RPB, 320>>>();
    k_final<<<1, 256>>>(out);
}

// round 16
// speedup vs baseline: 1.0986x; 1.0743x over previous
#include <cuda_runtime.h>
#include <cuda_fp16.h>
#include <math.h>
#include <stdint.h>

#define SN 6400
#define CC 256
#define NBATCH 2
#define LOG2E10 14.426950408889634f    // 10 * log2(e)

// ---------------- scratch (device globals; no allocation allowed) ----------
__device__ __align__(16) __half g_A[NBATCH * SN * CC];    // normalized I, fp16
__device__ __align__(16) __half g_B[NBATCH * SN * CC];    // normalized T, fp16
__device__ __align__(16) __half g_rawh[(size_t)NBATCH * SN * SN]; // raw matrix fp16
__device__ float    g_mean[CC];
__device__ unsigned g_rowmin[NBATCH * SN];                // row min bits (raw>=0)
__device__ unsigned g_colmax[NBATCH * SN];                // encoded float max

// order-preserving float <-> uint encoding (atomicMax on floats)
__device__ __forceinline__ unsigned enc_f(float f) {
    unsigned u = __float_as_uint(f);
    return (u & 0x80000000u) ? ~u : (u | 0x80000000u);
}
__device__ __forceinline__ float dec_f(unsigned u) {
    u = (u & 0x80000000u) ? (u ^ 0x80000000u) : ~u;
    return __uint_as_float(u);
}

// fast exp2 via MUFU (device-guaranteed, independent of fast-math flags)
__device__ __forceinline__ float ex2(float x) {
    float r;
    asm("ex2.approx.f32 %0, %1;" : "=f"(r) : "f"(x));
    return r;
}

// ---------------- PTX helpers (plain sm_80-era, no arch-variant gating) ----
__device__ __forceinline__ uint32_t smem_u32(const void* p) {
    uint32_t a;
    asm("{ .reg .u64 t; cvta.to.shared.u64 t, %1; cvt.u32.u64 %0, t; }" : "=r"(a) : "l"(p));
    return a;
}
__device__ __forceinline__ void cp16(uint32_t dst, const void* src) {
    asm volatile("cp.async.cg.shared.global [%0], [%1], 16;" :: "r"(dst), "l"(src));
}
#define CP_COMMIT() asm volatile("cp.async.commit_group;" ::: "memory")
#define CP_WAIT2()  asm volatile("cp.async.wait_group 2;" ::: "memory")

__device__ __forceinline__ void ldsm4(uint32_t r[4], uint32_t a) {
    asm volatile("ldmatrix.sync.aligned.m8n8.x4.shared.b16 {%0,%1,%2,%3}, [%4];"
        : "=r"(r[0]), "=r"(r[1]), "=r"(r[2]), "=r"(r[3]) : "r"(a));
}
__device__ __forceinline__ void mma_f16(float d[4], const uint32_t a[4],
                                        uint32_t b0, uint32_t b1) {
    asm volatile("mma.sync.aligned.m16n8k16.row.col.f32.f16.f16.f32 "
        "{%0,%1,%2,%3}, {%4,%5,%6,%7}, {%8,%9}, {%0,%1,%2,%3};"
        : "+f"(d[0]), "+f"(d[1]), "+f"(d[2]), "+f"(d[3])
        : "r"(a[0]), "r"(a[1]), "r"(a[2]), "r"(a[3]), "r"(b0), "r"(b1));
}
// SW128 xor swizzle for 128B rows: bits[6:4] ^= bits[9:7]
__device__ __forceinline__ uint32_t sw128(uint32_t o) {
    return o ^ (((o >> 7) & 7u) << 4);
}

// ---------------- kernel 1: per-channel mean of T over (n,h,w) -------------
__global__ void k_mean(const float* __restrict__ T) {
    int c = blockIdx.x;
    float s = 0.f;
    const float* p0 = T + (size_t)c * SN;
    const float* p1 = T + (size_t)(CC + c) * SN;
    for (int idx = threadIdx.x; idx < SN; idx += 256) s += p0[idx] + p1[idx];
    __shared__ float sh[256];
    sh[threadIdx.x] = s;
    __syncthreads();
    for (int o = 128; o > 0; o >>= 1) {
        if (threadIdx.x < o) sh[threadIdx.x] += sh[threadIdx.x + o];
        __syncthreads();
    }
    if (threadIdx.x == 0) g_mean[c] = sh[0] * (1.f / (NBATCH * SN));
}

// ---------------- kernel 2: center, normalize, fp16 out; init minima -------
__global__ void __launch_bounds__(256) k_norm(const float* __restrict__ I,
                                              const float* __restrict__ T) {
    __shared__ float smI[256][33];
    __shared__ float smT[256][33];
    __shared__ float part[2][32][8];
    __shared__ float rs[32][2];

    int n  = blockIdx.y;
    int s0 = blockIdx.x * 32;
    int tid = threadIdx.x;

    if (tid < 32) {
        g_colmax[n * SN + s0 + tid] = enc_f(-1e30f);
        g_rowmin[n * SN + s0 + tid] = 0x7F800000u;   // +inf
    }

#pragma unroll
    for (int it = 0; it < 8; it++) {
        int e  = tid + it * 256;            // 0..2047 granules
        int c  = e >> 3;                    // channel
        int s4 = (e & 7) * 4;               // 4 consecutive s
        float m = g_mean[c];
        size_t ga = ((size_t)n * CC + c) * SN + s0 + s4;
        float4 iv = *(const float4*)(I + ga);
        float4 tv = *(const float4*)(T + ga);
        smI[c][s4 + 0] = iv.x - m; smI[c][s4 + 1] = iv.y - m;
        smI[c][s4 + 2] = iv.z - m; smI[c][s4 + 3] = iv.w - m;
        smT[c][s4 + 0] = tv.x - m; smT[c][s4 + 1] = tv.y - m;
        smT[c][s4 + 2] = tv.z - m; smT[c][s4 + 3] = tv.w - m;
    }
    __syncthreads();
    {
        int s = tid & 31;
        int p = tid >> 5;
        float si = 0.f, st = 0.f;
#pragma unroll
        for (int q = 0; q < 32; q++) {
            int c = p * 32 + q;
            float a = smI[c][s];
            float b = smT[c][s];
            si += a * a;
            st += b * b;
        }
        part[0][s][p] = si;
        part[1][s][p] = st;
    }
    __syncthreads();
    if (tid < 32) {
        float si = 0.f, st = 0.f;
#pragma unroll
        for (int p = 0; p < 8; p++) { si += part[0][tid][p]; st += part[1][tid][p]; }
        rs[tid][0] = rsqrtf(si);
        rs[tid][1] = rsqrtf(st);
    }
    __syncthreads();
#pragma unroll
    for (int it = 0; it < 16; it++) {
        int e = tid + it * 256;
        int s  = e >> 7;
        int cp = (e & 127) * 2;
        float ri = rs[s][0];
        float rt = rs[s][1];
        size_t ob = ((size_t)n * SN + s0 + s) * CC + cp;
        *(__half2*)(g_A + ob) = __floats2half2_rn(smI[cp][s] * ri, smI[cp + 1][s] * ri);
        *(__half2*)(g_B + ob) = __floats2half2_rn(smT[cp][s] * rt, smT[cp + 1][s] * rt);
    }
}

// ---------------- kernel 3: fp16 mma GEMM (fp32 acc), rawh + row minima ----
// CTA tile 128x128, 128 threads = 4 warps of 64x64 (LDSM per MMA down 33%),
// BK=64 (128B rows, SW128), 3-stage cp.async pipeline.
#define TILE_B 16384               // 128 rows x 128 bytes
#define STAGE_B (2 * TILE_B)       // A, B
#define NSTAGE 3
#define GEMM_SMEM (NSTAGE * STAGE_B)   // 96 KB

__global__ void __launch_bounds__(128, 2) k_gemm_mma() {
    extern __shared__ __align__(1024) char smb[];
    int tid = threadIdx.x;
    int wid = tid >> 5;
    int l   = tid & 31;
    int n  = blockIdx.z;
    int i0 = blockIdx.y * 128;
    int j0 = blockIdx.x * 128;
    uint32_t sbase = smem_u32(smb);

    auto load_stage = [&](int kc, int s) {
        int k0 = kc * 64;
        uint32_t b = sbase + s * STAGE_B;
#pragma unroll
        for (int i = 0; i < 8; i++) {
            int e   = tid + i * 128;       // 0..1023 granules
            int row = e >> 3;
            int ch  = e & 7;
            uint32_t so = sw128((uint32_t)(row * 128 + ch * 16));
            cp16(b + so,          g_A + (size_t)(n * SN + i0 + row) * CC + k0 + ch * 8);
            cp16(b + TILE_B + so, g_B + (size_t)(n * SN + j0 + row) * CC + k0 + ch * 8);
        }
        CP_COMMIT();
    };

    float acc[4][8][4];
#pragma unroll
    for (int a = 0; a < 4; a++)
#pragma unroll
        for (int g = 0; g < 8; g++)
#pragma unroll
            for (int q = 0; q < 4; q++) acc[a][g][q] = 0.f;

    int wm = wid >> 1;                 // 0..1
    int wn = wid & 1;                  // 0..1
    int mb = wm * 64;
    int nb = wn * 64;

    int a_row0 = mb + (l & 15);
    int a_ch   = l >> 4;
    int b_ch   = (l >> 3) & 1;
    int b_rowq = nb + (l & 7) + ((l >> 4) << 3);

    load_stage(0, 0);
    load_stage(1, 1);
    load_stage(2, 2);

#pragma unroll
    for (int kc = 0; kc < 4; kc++) {
        CP_WAIT2();
        __syncthreads();
        uint32_t b = sbase + (kc % NSTAGE) * STAGE_B;
#pragma unroll
        for (int ks = 0; ks < 4; ks++) {
            uint32_t ah[4][4], bt[4][4];
#pragma unroll
            for (int mt = 0; mt < 4; mt++) {
                uint32_t off = sw128((uint32_t)((a_row0 + mt * 16) * 128 + ks * 32 + a_ch * 16));
                ldsm4(ah[mt], b + off);
            }
#pragma unroll
            for (int ng = 0; ng < 4; ng++) {
                uint32_t off = sw128((uint32_t)((b_rowq + ng * 16) * 128 + ks * 32 + b_ch * 16));
                ldsm4(bt[ng], b + TILE_B + off);
            }
#pragma unroll
            for (int mt = 0; mt < 4; mt++)
#pragma unroll
                for (int ng = 0; ng < 4; ng++) {
                    mma_f16(acc[mt][2 * ng],     ah[mt], bt[ng][0], bt[ng][1]);
                    mma_f16(acc[mt][2 * ng + 1], ah[mt], bt[ng][2], bt[ng][3]);
                }
        }
        __syncthreads();
        if (kc + 3 < 4) load_stage(kc + 3, kc % NSTAGE);
        else            CP_COMMIT();       // keep group FIFO advancing
    }

    // ---- epilogue: rawh = clip((1-cos)/2, 0) + per-row min -> g_rowmin ----
    __half* out = g_rawh + (size_t)n * SN * SN;
    int r0 = i0 + mb + (l >> 2);
    int c0 = j0 + nb + (l & 3) * 2;
#pragma unroll
    for (int mt = 0; mt < 4; mt++) {
        int r = r0 + mt * 16;
        float rm0 = 1e30f, rm1 = 1e30f;
#pragma unroll
        for (int g = 0; g < 8; g++) {
            int c = c0 + g * 8;
            float v0 = fmaxf(0.5f * (1.f - acc[mt][g][0]), 0.f);
            float v1 = fmaxf(0.5f * (1.f - acc[mt][g][1]), 0.f);
            float v2 = fmaxf(0.5f * (1.f - acc[mt][g][2]), 0.f);
            float v3 = fmaxf(0.5f * (1.f - acc[mt][g][3]), 0.f);
            rm0 = fminf(rm0, fminf(v0, v1));
            rm1 = fminf(rm1, fminf(v2, v3));
            *(__half2*)(out + (size_t)r * SN + c)       = __floats2half2_rn(v0, v1);
            *(__half2*)(out + (size_t)(r + 8) * SN + c) = __floats2half2_rn(v2, v3);
        }
        // quad reduce (lanes l^1, l^2 share the same rows)
#pragma unroll
        for (int o = 1; o <= 2; o <<= 1) {
            rm0 = fminf(rm0, __shfl_xor_sync(~0u, rm0, o));
            rm1 = fminf(rm1, __shfl_xor_sync(~0u, rm1, o));
        }
        if ((l & 3) == 0) {
            atomicMin(&g_rowmin[n * SN + r],     __float_as_uint(rm0));
            atomicMin(&g_rowmin[n * SN + r + 8], __float_as_uint(rm1));
        }
    }
}

// ---------------- kernel 4: fused Z + column max (row min precomputed) -----
// 320 threads, 32 rows/block, 2 rows per iter, ONE barrier per iter (parity
// double-buffered slots). Base-2 softmax. Regs capped for 3 CTAs/SM.
#define RPB 32
__global__ void __launch_bounds__(320, 3) k_stats() {
    __shared__ float red_z[2][2][10];    // [parity][row-of-pair][warp]

    int tid  = threadIdx.x;
    int lane = tid & 31;
    int warp = tid >> 5;                 // 0..9
    int rbase = blockIdx.x * RPB;        // global row id
    int n = rbase / SN;

    __half2 cm[10];
#pragma unroll
    for (int q = 0; q < 10; q++) cm[q] = __float2half2_rn(-60000.f);

    const __half2* rowbase = (const __half2*)g_rawh + (size_t)rbase * (SN / 2);

    for (int r = 0; r < RPB; r += 2) {
        int par = (r >> 1) & 1;
        const __half2* row0 = rowbase + (size_t)r * (SN / 2);
        const __half2* row1 = row0 + (SN / 2);
        __half2 v[10], w[10];
#pragma unroll
        for (int q = 0; q < 10; q++) { v[q] = row0[tid + q * 320]; w[q] = row1[tid + q * 320]; }

        // a2 = 10*log2(e)/(rmin+eps); exponent in base 2
        float av = LOG2E10 / (__uint_as_float(g_rowmin[rbase + r])     + 1e-5f);
        float aw = LOG2E10 / (__uint_as_float(g_rowmin[rbase + r + 1]) + 1e-5f);

        float zv = 0.f, zw = 0.f;
#pragma unroll
        for (int q = 0; q < 10; q++) {
            float2 fv = __half22float2(v[q]);
            float2 fw = __half22float2(w[q]);
            zv += ex2(LOG2E10 - av * fv.x) + ex2(LOG2E10 - av * fv.y);
            zw += ex2(LOG2E10 - aw * fw.x) + ex2(LOG2E10 - aw * fw.y);
        }
#pragma unroll
        for (int o = 16; o > 0; o >>= 1) {
            zv += __shfl_xor_sync(~0u, zv, o);
            zw += __shfl_xor_sync(~0u, zw, o);
        }
        if (lane == 0) { red_z[par][0][warp] = zv; red_z[par][1][warp] = zw; }
        __syncthreads();
        float Zv = red_z[par][0][0], Zw = red_z[par][1][0];
#pragma unroll
        for (int x = 1; x < 10; x++) { Zv += red_z[par][0][x]; Zw += red_z[par][1][x]; }
        float c0v = LOG2E10 - __log2f(Zv);   // log2-space offset
        float c0w = LOG2E10 - __log2f(Zw);

#pragma unroll
        for (int q = 0; q < 10; q++) {
            float2 fv = __half22float2(v[q]);
            float2 fw = __half22float2(w[q]);
            cm[q] = __hmax2(cm[q], __floats2half2_rn(c0v - av * fv.x, c0v - av * fv.y));
            cm[q] = __hmax2(cm[q], __floats2half2_rn(c0w - aw * fw.x, c0w - aw * fw.y));
        }
    }

#pragma unroll
    for (int q = 0; q < 10; q++) {
        float2 f = __half22float2(cm[q]);   // log2-space colmax
        int j = 2 * (tid + q * 320);
        atomicMax(&g_colmax[n * SN + j],     enc_f(f.x));
        atomicMax(&g_colmax[n * SN + j + 1], enc_f(f.y));
    }
}

// ---------------- kernel 5: final reduction -> loss (base-2 colmax) --------
__global__ void k_final(float* __restrict__ out) {
    __shared__ float2 sh[256];
    int tid = threadIdx.x;
    float s0 = 0.f, s1 = 0.f;
    for (int j = tid; j < SN; j += 256) {
        s0 += ex2(dec_f(g_colmax[j]));
        s1 += ex2(dec_f(g_colmax[SN + j]));
    }
    sh[tid] = make_float2(s0, s1);
    __syncthreads();
    for (int o = 128; o > 0; o >>= 1) {
        if (tid < o) { sh[tid].x += sh[tid + o].x; sh[tid].y += sh[tid + o].y; }
        __syncthreads();
    }
    if (tid == 0) {
        float cs0 = sh[0].x * (1.f / SN);
        float cs1 = sh[0].y * (1.f / SN);
        out[0] = -0.5f * (logf(cs0) + logf(cs1));
    }
}

// ---------------- launcher --------------------------------------------------
extern "C" void kernel_launch(void* const* d_in, const int* in_sizes, int n_in,
                              void* d_out, int out_size) {
    const float* I = (const float*)d_in[0];
    const float* T = (const float*)d_in[1];
    float* out = (float*)d_out;

    cudaFuncSetAttribute(k_gemm_mma, cudaFuncAttributeMaxDynamicSharedMemorySize, GEMM_SMEM);

    k_mean<<<CC, 256>>>(T);
    k_norm<<<dim3(SN / 32, NBATCH), 256>>>(I, T);
    dim3 gg(SN / 128, SN / 128, NBATCH);
    k_gemm_mma<<<gg, 128, GEMM_SMEM>>>();
    k_stats<<<NBATCH * SN / RPB, 320>>>();
    k_final<<<1, 256>>>(out);
}